// round 1
// baseline (speedup 1.0000x reference)
#include <cuda_runtime.h>

#define BB 128
#define TT 512
#define CC 128
#define NTH 256

__device__ float g_partial[BB];

__global__ __launch_bounds__(NTH, 1)
void crf_forward_kernel(const float* __restrict__ feats,
                        const int*   __restrict__ mask,
                        const int*   __restrict__ tags,
                        const float* __restrict__ trans)
{
    const int b   = blockIdx.x;
    const int tid = threadIdx.x;
    const int j   = tid & 127;   // class column owned
    const int h   = tid >> 7;    // which half of i-range (0 or 1)

    __shared__ float p_s[CC];        // exp(alpha - m)
    __shared__ float red_s[NTH];     // partial sums / reductions
    __shared__ float wmax_s[4];
    __shared__ int   L_s;

    // ---- sequence length (contiguous prefix mask) ----
    {
        int cnt = 0;
        const int* mrow = mask + b * TT;
        for (int t = tid; t < TT; t += NTH) cnt += mrow[t];
        #pragma unroll
        for (int o = 16; o > 0; o >>= 1)
            cnt += __shfl_xor_sync(0xffffffffu, cnt, o);
        if (tid == 0) L_s = 0;
        __syncthreads();
        if ((tid & 31) == 0) atomicAdd(&L_s, cnt);
        __syncthreads();
    }
    const int L = L_s;

    // ---- load E column-half into registers: Ereg[ii] = exp(trans[h*64+ii][j]) ----
    float Ereg[64];
    #pragma unroll
    for (int ii = 0; ii < 64; ii++)
        Ereg[ii] = expf(trans[(h * 64 + ii) * CC + j]);

    // ---- init: alpha0 = -10000 except START(C-2)=0 ; centered at m=0 ----
    if (h == 0) p_s[j] = (j == CC - 2) ? 1.0f : 0.0f;
    float m = 0.0f;
    __syncthreads();

    const float* fb = feats + (size_t)b * TT * CC;
    float feat_cur = (L > 0) ? fb[j] : 0.0f;

    // ---- forward scan ----
    for (int t = 0; t < L; t++) {
        float feat_next = (t + 1 < L) ? fb[(t + 1) * CC + j] : 0.0f;

        // matvec half: acc = sum_{i in half} p[i] * E[i][j]
        float a0 = 0.f, a1 = 0.f, a2 = 0.f, a3 = 0.f;
        const float4* pv = (const float4*)(p_s + h * 64);
        #pragma unroll
        for (int ii = 0; ii < 16; ii++) {
            float4 p4 = pv[ii];
            a0 = fmaf(p4.x, Ereg[4 * ii + 0], a0);
            a1 = fmaf(p4.y, Ereg[4 * ii + 1], a1);
            a2 = fmaf(p4.z, Ereg[4 * ii + 2], a2);
            a3 = fmaf(p4.w, Ereg[4 * ii + 3], a3);
        }
        red_s[tid] = (a0 + a1) + (a2 + a3);
        __syncthreads();

        // v_j = log(s_j) + feat_j   (both halves compute identically)
        float s = red_s[j] + red_s[j + 128];
        float v = logf(s) + feat_cur;

        // max over j (warps 0-3 and 4-7 hold duplicate j-coverage; benign dup writes)
        float vmax = v;
        #pragma unroll
        for (int o = 16; o > 0; o >>= 1)
            vmax = fmaxf(vmax, __shfl_xor_sync(0xffffffffu, vmax, o));
        if ((tid & 31) == 0) wmax_s[(tid >> 5) & 3] = vmax;
        __syncthreads();

        float mx = fmaxf(fmaxf(wmax_s[0], wmax_s[1]),
                         fmaxf(wmax_s[2], wmax_s[3]));
        if (h == 0) p_s[j] = expf(v - mx);
        m += mx;
        feat_cur = feat_next;
        __syncthreads();
    }

    // ---- logZ = m + log( sum_j p_j * exp(trans[j][STOP]) ) ----
    float contrib = 0.0f;
    if (h == 0) contrib = p_s[j] * expf(trans[j * CC + (CC - 1)]);
    red_s[tid] = contrib;
    __syncthreads();
    #pragma unroll
    for (int off = 128; off > 0; off >>= 1) {
        if (tid < off) red_s[tid] += red_s[tid + off];
        __syncthreads();
    }
    float logZ = m + logf(red_s[0]);
    __syncthreads();

    // ---- gold path score ----
    const int* tg = tags + b * TT;
    float sc = 0.0f;
    for (int t = tid; t < L; t += NTH)
        sc += fb[t * CC + tg[t]];                       // emission score
    for (int k = tid; k <= L; k += NTH) {               // transition score
        int prev = (k == 0) ? (CC - 2) : tg[k - 1];
        int cur  = (k == L) ? (CC - 1) : tg[k];
        sc += trans[prev * CC + cur];
    }
    red_s[tid] = sc;
    __syncthreads();
    #pragma unroll
    for (int off = 128; off > 0; off >>= 1) {
        if (tid < off) red_s[tid] += red_s[tid + off];
        __syncthreads();
    }

    if (tid == 0) g_partial[b] = logZ - red_s[0];
}

__global__ void crf_finalize_kernel(float* __restrict__ out)
{
    __shared__ float s[BB];
    int tid = threadIdx.x;
    s[tid] = g_partial[tid];
    __syncthreads();
    #pragma unroll
    for (int off = 64; off > 0; off >>= 1) {
        if (tid < off) s[tid] += s[tid + off];
        __syncthreads();
    }
    if (tid == 0) out[0] = s[0] / (float)BB;
}

extern "C" void kernel_launch(void* const* d_in, const int* in_sizes, int n_in,
                              void* d_out, int out_size)
{
    const float* feats = (const float*)d_in[0];
    const int*   mask  = (const int*)  d_in[1];
    const int*   tags  = (const int*)  d_in[2];
    const float* trans = (const float*)d_in[3];
    float* out = (float*)d_out;

    crf_forward_kernel<<<BB, NTH>>>(feats, mask, tags, trans);
    crf_finalize_kernel<<<1, BB>>>(out);
}

// round 2
// speedup vs baseline: 2.0621x; 2.0621x over previous
#include <cuda_runtime.h>

#define BB 128
#define TT 512
#define CC 128

__device__ float g_partial[BB];

__device__ __forceinline__ float block_reduce_sum_128(float v, float* sh4) {
    #pragma unroll
    for (int o = 16; o > 0; o >>= 1)
        v += __shfl_xor_sync(0xffffffffu, v, o);
    int w = threadIdx.x >> 5;
    if ((threadIdx.x & 31) == 0) sh4[w] = v;
    __syncthreads();
    float r = (sh4[0] + sh4[1]) + (sh4[2] + sh4[3]);
    __syncthreads();
    return r;
}

__global__ __launch_bounds__(128, 1)
void crf_forward_kernel(const float* __restrict__ feats,
                        const int*   __restrict__ mask,
                        const int*   __restrict__ tags,
                        const float* __restrict__ trans)
{
    const int b = blockIdx.x;
    const int j = threadIdx.x;          // owns class column j

    __shared__ float p_s[2][CC];
    __shared__ float sh4[4];

    // ---- sequence length (contiguous prefix mask) ----
    const int* mrow = mask + b * TT;
    int cnt = 0;
    #pragma unroll
    for (int t = 0; t < 4; t++) cnt += mrow[j + t * 128];
    const int L = (int)block_reduce_sum_128((float)cnt, sh4);

    // ---- full E column in registers: Ereg[i] = exp(trans[i][j]) ----
    float Ereg[CC];
    #pragma unroll
    for (int i = 0; i < CC; i++)
        Ereg[i] = __expf(trans[i * CC + j]);   // exp(-1e5) flushes to exactly 0

    // ---- init: p = one-hot(START), m = 0 ----
    p_s[0][j] = (j == CC - 2) ? 1.0f : 0.0f;
    __syncthreads();

    const float* fb = feats + (size_t)b * TT * CC + j;
    float m  = 0.0f;
    float f0 = fb[0];                               // L >= 1 always
    float f1 = (L > 1) ? fb[CC] : 0.0f;
    int cur = 0;

    // ---- forward scan: one barrier per step, no max-reduction ----
    for (int t = 0; t < L; t++) {
        float f2 = (t + 2 < L) ? fb[(size_t)(t + 2) * CC] : 0.0f;

        const float4* pv = (const float4*)p_s[cur];
        float a0 = 0.f, a1 = 0.f, a2 = 0.f, a3 = 0.f;
        #pragma unroll
        for (int ii = 0; ii < 32; ii++) {
            float4 p4 = pv[ii];
            a0 = fmaf(p4.x, Ereg[4 * ii + 0], a0);
            a1 = fmaf(p4.y, Ereg[4 * ii + 1], a1);
            a2 = fmaf(p4.z, Ereg[4 * ii + 2], a2);
            a3 = fmaf(p4.w, Ereg[4 * ii + 3], a3);
        }
        float s = (a0 + a1) + (a2 + a3);

        // scale by previous p[0] (broadcast read, no reduction needed:
        // all live entries stay within ~e^20 of each other)
        float c  = (t == 0) ? 1.0f : p_s[cur][0];
        float lc = __logf(c);
        p_s[cur ^ 1][j] = s * __expf(f0 - lc);
        m += lc;

        f0 = f1; f1 = f2;
        cur ^= 1;
        __syncthreads();
    }

    // ---- logZ = m + log( sum_j p[j] * exp(trans[j][STOP]) ) ----
    float contrib = p_s[cur][j] * __expf(trans[j * CC + (CC - 1)]);
    float tot = block_reduce_sum_128(contrib, sh4);
    float logZ = m + __logf(tot);

    // ---- gold path score ----
    const int* tg = tags + b * TT;
    const float* fbase = feats + (size_t)b * TT * CC;
    float sc = 0.0f;
    for (int t = j; t < L; t += 128)
        sc += fbase[(size_t)t * CC + tg[t]];
    for (int k = j; k <= L; k += 128) {
        int prev = (k == 0) ? (CC - 2) : tg[k - 1];
        int curt = (k == L) ? (CC - 1) : tg[k];
        sc += trans[prev * CC + curt];
    }
    float tots = block_reduce_sum_128(sc, sh4);

    if (j == 0) g_partial[b] = logZ - tots;
}

__global__ void crf_finalize_kernel(float* __restrict__ out)
{
    __shared__ float s[BB];
    int tid = threadIdx.x;
    s[tid] = g_partial[tid];
    __syncthreads();
    #pragma unroll
    for (int off = 64; off > 0; off >>= 1) {
        if (tid < off) s[tid] += s[tid + off];
        __syncthreads();
    }
    if (tid == 0) out[0] = s[0] / (float)BB;
}

extern "C" void kernel_launch(void* const* d_in, const int* in_sizes, int n_in,
                              void* d_out, int out_size)
{
    const float* feats = (const float*)d_in[0];
    const int*   mask  = (const int*)  d_in[1];
    const int*   tags  = (const int*)  d_in[2];
    const float* trans = (const float*)d_in[3];
    float* out = (float*)d_out;

    crf_forward_kernel<<<BB, 128>>>(feats, mask, tags, trans);
    crf_finalize_kernel<<<1, BB>>>(out);
}